// round 1
// baseline (speedup 1.0000x reference)
#include <cuda_runtime.h>
#include <cstdint>

// Problem constants (from reference):
//   inputs: (B=8, H=160, W=160, C=256) fp32, NHWC
//   rois:   (N=1024, 5) fp32  [img_id, x0, y0, x1, y1] in image pixels
//   im_info:(N, 2) fp32       [H_img, W_img]
//   output: (N, 7, 7, 256) fp32 = crop_and_resize(14x14) -> maxpool 2x2 s2 SAME
//
// d_in[0] = inputs, d_in[1] = rois, d_in[2] = im_info (setup_inputs dict order)

#define FEAT_H 160
#define FEAT_W 160
#define FEAT_C 256
#define CROP   14
#define POOL   7

__global__ __launch_bounds__(64, 16)
void roipool_kernel(const float* __restrict__ in,
                    const float* __restrict__ rois,
                    const float* __restrict__ im_info,
                    float* __restrict__ out)
{
    const int blk = blockIdx.x;            // roi * 49 + pooled_pixel
    const int roi = blk / 49;
    const int pix = blk - roi * 49;
    const int py  = pix / POOL;
    const int px  = pix - py * POOL;
    const int t   = threadIdx.x;           // 0..63, float4 channel lane

    // --- ROI parameters (warp-uniform broadcast loads) ---
    const float b_f   = __ldg(&rois[roi * 5 + 0]);
    const float H_img = __ldg(&im_info[roi * 2 + 0]);
    const float W_img = __ldg(&im_info[roi * 2 + 1]);
    const float x1 = __ldg(&rois[roi * 5 + 1]) / W_img;
    const float y1 = __ldg(&rois[roi * 5 + 2]) / H_img;
    const float x2 = __ldg(&rois[roi * 5 + 3]) / W_img;
    const float y2 = __ldg(&rois[roi * 5 + 4]) / H_img;
    const int   b  = (int)b_f;

    // Reference arithmetic order: y1*(Hf-1) + iy * ((y2-y1)*(Hf-1)/(ch-1))
    const float Hm1 = (float)(FEAT_H - 1);   // 159
    const float Wm1 = (float)(FEAT_W - 1);   // 159
    const float sy = (y2 - y1) * Hm1 / (float)(CROP - 1);
    const float sx = (x2 - x1) * Wm1 / (float)(CROP - 1);
    const float by = y1 * Hm1;
    const float bx = x1 * Wm1;

    const float NEG_INF = __int_as_float(0xff800000);
    float4 vmax = make_float4(NEG_INF, NEG_INF, NEG_INF, NEG_INF);

    #pragma unroll
    for (int dy = 0; dy < 2; ++dy) {
        const int   cy = 2 * py + dy;
        const float y  = by + (float)cy * sy;
        const bool  vy = (y >= 0.0f) && (y <= Hm1);
        const float yf = floorf(y);
        const float ylerp = y - yf;
        const int   yl = min(max((int)yf, 0), FEAT_H - 1);
        const int   yh = min(max((int)yf + 1, 0), FEAT_H - 1);

        #pragma unroll
        for (int dx = 0; dx < 2; ++dx) {
            const int   cx = 2 * px + dx;
            const float x  = bx + (float)cx * sx;
            const bool  vv = vy && (x >= 0.0f) && (x <= Wm1);
            const float xf = floorf(x);
            const float xlerp = x - xf;
            const int   xl = min(max((int)xf, 0), FEAT_W - 1);
            const int   xh = min(max((int)xf + 1, 0), FEAT_W - 1);

            float4 v;
            if (vv) {
                const size_t rb = ((size_t)b * FEAT_H) * FEAT_W;
                const float4* ptl = (const float4*)(in + ((rb + (size_t)yl * FEAT_W + xl) * FEAT_C)) + t;
                const float4* ptr = (const float4*)(in + ((rb + (size_t)yl * FEAT_W + xh) * FEAT_C)) + t;
                const float4* pbl = (const float4*)(in + ((rb + (size_t)yh * FEAT_W + xl) * FEAT_C)) + t;
                const float4* pbr = (const float4*)(in + ((rb + (size_t)yh * FEAT_W + xh) * FEAT_C)) + t;
                const float4 tl = __ldg(ptl);
                const float4 tr = __ldg(ptr);
                const float4 bl = __ldg(pbl);
                const float4 br = __ldg(pbr);
                // top = tl + (tr-tl)*xlerp ; bot = bl + (br-bl)*xlerp ; out = top + (bot-top)*ylerp
                float tx, bx2;
                tx  = tl.x + (tr.x - tl.x) * xlerp;  bx2 = bl.x + (br.x - bl.x) * xlerp;  v.x = tx + (bx2 - tx) * ylerp;
                tx  = tl.y + (tr.y - tl.y) * xlerp;  bx2 = bl.y + (br.y - bl.y) * xlerp;  v.y = tx + (bx2 - tx) * ylerp;
                tx  = tl.z + (tr.z - tl.z) * xlerp;  bx2 = bl.z + (br.z - bl.z) * xlerp;  v.z = tx + (bx2 - tx) * ylerp;
                tx  = tl.w + (tr.w - tl.w) * xlerp;  bx2 = bl.w + (br.w - bl.w) * xlerp;  v.w = tx + (bx2 - tx) * ylerp;
            } else {
                v = make_float4(0.0f, 0.0f, 0.0f, 0.0f);
            }
            vmax.x = fmaxf(vmax.x, v.x);
            vmax.y = fmaxf(vmax.y, v.y);
            vmax.z = fmaxf(vmax.z, v.z);
            vmax.w = fmaxf(vmax.w, v.w);
        }
    }

    float4* o = (float4*)(out + (size_t)blk * FEAT_C) + t;
    *o = vmax;
}

extern "C" void kernel_launch(void* const* d_in, const int* in_sizes, int n_in,
                              void* d_out, int out_size)
{
    const float* in      = (const float*)d_in[0];
    const float* rois    = (const float*)d_in[1];
    const float* im_info = (const float*)d_in[2];
    float* out           = (float*)d_out;

    const int N = in_sizes[1] / 5;   // 1024
    dim3 grid(N * POOL * POOL);      // 50176 blocks
    dim3 block(64);                  // 64 threads x float4 = 256 channels
    roipool_kernel<<<grid, block>>>(in, rois, im_info, out);
}